// round 1
// baseline (speedup 1.0000x reference)
#include <cuda_runtime.h>
#include <math.h>

// Problem: DistributionLoss — local 7x7xC std of two [16,3,512,512] tensors,
// smooth-L1 between the std maps, global mean. HBM-bound (~100 MB reads).
//
// Strategy: per-block 32x32 tile + 3-halo. Channel-sum (s, s2) at load time,
// separable 7-tap box sums in smem, std per pixel for pred then tgt (smem
// reused), smooth-L1 accumulated, deterministic two-stage reduction.

#define TILE   32
#define HALO   3
#define HSZ    (TILE + 2 * HALO)   // 38
#define SPITCH (HSZ + 2)           // 40, pad to avoid conflicts
#define KK     7
#define NDIV   147.0f              // C*K*K = 3*49
#define EPS    1e-8f
#define HW     (512 * 512)
#define NPIX   (16.0f * 512.0f * 512.0f)

__device__ float g_partials[4096];

struct TileStd {
    float v[4];
};

// Computes local std for the block's 32x32 tile of tensor `x` (one batch image),
// result per thread in out.v[0..3] for rows ty, ty+8, ty+16, ty+24 at col tx.
__device__ __forceinline__ void local_std_tile(
    const float* __restrict__ x,   // base of this batch image: [3,512,512]
    int x0, int y0, int tx, int ty,
    float s_raw[HSZ][SPITCH], float s_raw2[HSZ][SPITCH],
    float s_v[TILE][SPITCH],  float s_v2[TILE][SPITCH],
    TileStd& out)
{
    // Phase 1: load halo, summing over channels. One global read per element.
    for (int r = ty; r < HSZ; r += 8) {
        int gy = y0 - HALO + r;
        bool rowok = (unsigned)gy < 512u;
        for (int c = tx; c < HSZ; c += 32) {
            int gx = x0 - HALO + c;
            float s = 0.f, s2 = 0.f;
            if (rowok && (unsigned)gx < 512u) {
                int idx = gy * 512 + gx;
                float v0 = x[idx];
                float v1 = x[HW + idx];
                float v2 = x[2 * HW + idx];
                s  = v0 + v1 + v2;
                s2 = v0 * v0 + v1 * v1 + v2 * v2;
            }
            s_raw [r][c] = s;
            s_raw2[r][c] = s2;
        }
    }
    __syncthreads();

    // Phase 2: vertical 7-tap sums (output rows x halo cols).
    for (int r = ty; r < TILE; r += 8) {
        for (int c = tx; c < HSZ; c += 32) {
            float a = 0.f, a2 = 0.f;
#pragma unroll
            for (int k = 0; k < KK; k++) {
                a  += s_raw [r + k][c];
                a2 += s_raw2[r + k][c];
            }
            s_v [r][c] = a;
            s_v2[r][c] = a2;
        }
    }
    __syncthreads();

    // Phase 3: horizontal 7-tap + std, 4 rows per thread.
#pragma unroll
    for (int j = 0; j < 4; j++) {
        int r = ty + j * 8;
        float S = 0.f, S2 = 0.f;
#pragma unroll
        for (int k = 0; k < KK; k++) {
            S  += s_v [r][tx + k];
            S2 += s_v2[r][tx + k];
        }
        float mu  = S * (1.0f / NDIV);
        float var = S2 * (1.0f / NDIV) - mu * mu;
        out.v[j] = sqrtf(var + EPS);
    }
    __syncthreads();  // smem will be reused by caller
}

__global__ __launch_bounds__(256)
void dist_loss_main(const float* __restrict__ pred,
                    const float* __restrict__ tgt)
{
    __shared__ float s_raw [HSZ][SPITCH];
    __shared__ float s_raw2[HSZ][SPITCH];
    __shared__ float s_v   [TILE][SPITCH];
    __shared__ float s_v2  [TILE][SPITCH];
    __shared__ float s_red[256];

    int tx = threadIdx.x;           // 0..31
    int ty = threadIdx.y;           // 0..7
    int x0 = blockIdx.x * TILE;
    int y0 = blockIdx.y * TILE;
    int b  = blockIdx.z;

    const float* pbase = pred + (size_t)b * 3 * HW;
    const float* tbase = tgt  + (size_t)b * 3 * HW;

    TileStd sp, st;
    local_std_tile(pbase, x0, y0, tx, ty, s_raw, s_raw2, s_v, s_v2, sp);
    local_std_tile(tbase, x0, y0, tx, ty, s_raw, s_raw2, s_v, s_v2, st);

    float acc = 0.f;
#pragma unroll
    for (int j = 0; j < 4; j++) {
        float d  = sp.v[j] - st.v[j];
        float ad = fabsf(d);
        acc += (ad < 1.0f) ? 0.5f * d * d : (ad - 0.5f);
    }

    // Deterministic block tree reduction over 256 threads.
    int tid = ty * 32 + tx;
    s_red[tid] = acc;
    __syncthreads();
#pragma unroll
    for (int s = 128; s > 0; s >>= 1) {
        if (tid < s) s_red[tid] += s_red[tid + s];
        __syncthreads();
    }
    if (tid == 0) {
        int pidx = b * 256 + blockIdx.y * 16 + blockIdx.x;
        g_partials[pidx] = s_red[0];
    }
}

__global__ __launch_bounds__(1024)
void dist_loss_reduce(float* __restrict__ out)
{
    __shared__ float s_red[1024];
    int tid = threadIdx.x;
    float a = g_partials[tid] + g_partials[tid + 1024] +
              g_partials[tid + 2048] + g_partials[tid + 3072];
    s_red[tid] = a;
    __syncthreads();
#pragma unroll
    for (int s = 512; s > 0; s >>= 1) {
        if (tid < s) s_red[tid] += s_red[tid + s];
        __syncthreads();
    }
    if (tid == 0) out[0] = s_red[0] * (1.0f / NPIX);
}

extern "C" void kernel_launch(void* const* d_in, const int* in_sizes, int n_in,
                              void* d_out, int out_size)
{
    const float* pred = (const float*)d_in[0];
    const float* tgt  = (const float*)d_in[1];
    float* out = (float*)d_out;

    dim3 grid(16, 16, 16);   // tiles_x, tiles_y, batch
    dim3 block(32, 8);
    dist_loss_main<<<grid, block>>>(pred, tgt);
    dist_loss_reduce<<<1, 1024>>>(out);
}

// round 2
// speedup vs baseline: 1.1830x; 1.1830x over previous
#include <cuda_runtime.h>
#include <math.h>

// DistributionLoss: local 7x7x3 std of two [16,3,512,512] f32 tensors,
// smooth-L1 between std maps, global mean.
//
// R2 design: 32x32 tile/block, channel-sum (s,s2) packed as float2 at load.
// Separable box sums with REGISTER sliding windows (4 outputs per 10-strip)
// in both directions -> ~2.2x less smem traffic than naive 7-tap passes.
// Deterministic two-stage reduction.

#define TILE   32
#define HALO   3
#define HSZ    38            // TILE + 2*HALO
#define RAWP   41            // raw pitch in float2 (bank-conflict-free for 4-col groups)
#define HSP    33            // hsum pitch in float2
#define NINV   (1.0f / 147.0f)   // 1/(C*K*K)
#define EPS    1e-8f
#define HW     (512 * 512)
#define NPIX   (16.0f * 512.0f * 512.0f)

__device__ float g_partials[4096];

__global__ __launch_bounds__(256)
void dist_loss_main(const float* __restrict__ pred,
                    const float* __restrict__ tgt)
{
    __shared__ float2 s_raw[HSZ * RAWP];   // (sum_c x, sum_c x^2), 38x38 halo tile
    __shared__ float2 s_hs [HSZ * HSP];    // horizontal 7-sums, 38 rows x 32 cols
    __shared__ float  s_red[256];

    const int tx  = threadIdx.x;           // 0..31
    const int ty  = threadIdx.y;           // 0..7
    const int tid = ty * 32 + tx;
    const int x0  = blockIdx.x * TILE;
    const int y0  = blockIdx.y * TILE;

    const float* base0 = pred + (size_t)blockIdx.z * 3 * HW;
    const float* base1 = tgt  + (size_t)blockIdx.z * 3 * HW;

    float stdv[2][4];

#pragma unroll
    for (int t = 0; t < 2; t++) {
        const float* x = (t == 0) ? base0 : base1;

        // ---- Phase 1: load halo, channel-summed, zero-padded ----
        for (int r = ty; r < HSZ; r += 8) {
            int gy = y0 - HALO + r;
            bool rowok = ((unsigned)gy < 512u);
            const float* rowp = x + gy * 512;
            for (int c = tx; c < HSZ; c += 32) {
                int gx = x0 - HALO + c;
                float s = 0.f, s2 = 0.f;
                if (rowok && ((unsigned)gx < 512u)) {
                    float v0 = rowp[gx];
                    float v1 = rowp[HW + gx];
                    float v2 = rowp[2 * HW + gx];
                    s  = v0 + v1 + v2;
                    s2 = v0 * v0 + v1 * v1 + v2 * v2;
                }
                s_raw[r * RAWP + c] = make_float2(s, s2);
            }
        }
        __syncthreads();

        // ---- Phase 2: horizontal 7-sum, register sliding window ----
        // thread -> (col group g: 4 cols, row rr); covers rows 0..31 then 32..37
        {
            int g  = tid & 7;        // 0..7  -> output cols 4g..4g+3
            int rr = tid >> 3;       // 0..31
#pragma unroll
            for (int rb = 0; rb < HSZ; rb += 32) {
                int r = rb + rr;
                if (r < HSZ) {
                    float2 e[10];
#pragma unroll
                    for (int i = 0; i < 10; i++)
                        e[i] = s_raw[r * RAWP + 4 * g + i];
                    float a = e[0].x + e[1].x + e[2].x + e[3].x + e[4].x + e[5].x + e[6].x;
                    float b = e[0].y + e[1].y + e[2].y + e[3].y + e[4].y + e[5].y + e[6].y;
#pragma unroll
                    for (int q = 0; q < 4; q++) {
                        s_hs[r * HSP + 4 * g + q] = make_float2(a, b);
                        if (q < 3) {
                            a += e[q + 7].x - e[q].x;
                            b += e[q + 7].y - e[q].y;
                        }
                    }
                }
            }
        }
        __syncthreads();

        // ---- Phase 3: vertical 7-sum + std, register sliding window ----
        // thread (tx, ty) -> col tx, output rows 4ty..4ty+3
        {
            float2 v[10];
#pragma unroll
            for (int i = 0; i < 10; i++)
                v[i] = s_hs[(4 * ty + i) * HSP + tx];
            float a = v[0].x + v[1].x + v[2].x + v[3].x + v[4].x + v[5].x + v[6].x;
            float b = v[0].y + v[1].y + v[2].y + v[3].y + v[4].y + v[5].y + v[6].y;
#pragma unroll
            for (int q = 0; q < 4; q++) {
                float mu  = a * NINV;
                float var = b * NINV - mu * mu;
                stdv[t][q] = sqrtf(var + EPS);
                if (q < 3) {
                    a += v[q + 7].x - v[q].x;
                    b += v[q + 7].y - v[q].y;
                }
            }
        }
        __syncthreads();   // protect s_hs/s_raw before next tensor reuses them
    }

    // ---- smooth-L1 over this thread's 4 pixels ----
    float acc = 0.f;
#pragma unroll
    for (int q = 0; q < 4; q++) {
        float d  = stdv[0][q] - stdv[1][q];
        float ad = fabsf(d);
        acc += (ad < 1.0f) ? 0.5f * d * d : (ad - 0.5f);
    }

    // ---- deterministic block reduction ----
    s_red[tid] = acc;
    __syncthreads();
#pragma unroll
    for (int s = 128; s > 0; s >>= 1) {
        if (tid < s) s_red[tid] += s_red[tid + s];
        __syncthreads();
    }
    if (tid == 0) {
        int pidx = blockIdx.z * 256 + blockIdx.y * 16 + blockIdx.x;
        g_partials[pidx] = s_red[0];
    }
}

__global__ __launch_bounds__(1024)
void dist_loss_reduce(float* __restrict__ out)
{
    __shared__ float s_red[1024];
    int tid = threadIdx.x;
    float a = g_partials[tid] + g_partials[tid + 1024] +
              g_partials[tid + 2048] + g_partials[tid + 3072];
    s_red[tid] = a;
    __syncthreads();
#pragma unroll
    for (int s = 512; s > 0; s >>= 1) {
        if (tid < s) s_red[tid] += s_red[tid + s];
        __syncthreads();
    }
    if (tid == 0) out[0] = s_red[0] * (1.0f / NPIX);
}

extern "C" void kernel_launch(void* const* d_in, const int* in_sizes, int n_in,
                              void* d_out, int out_size)
{
    const float* pred = (const float*)d_in[0];
    const float* tgt  = (const float*)d_in[1];
    float* out = (float*)d_out;

    dim3 grid(16, 16, 16);
    dim3 block(32, 8);
    dist_loss_main<<<grid, block>>>(pred, tgt);
    dist_loss_reduce<<<1, 1024>>>(out);
}

// round 3
// speedup vs baseline: 1.1870x; 1.0034x over previous
#include <cuda_runtime.h>
#include <math.h>

// DistributionLoss: local 7x7x3 std of two [16,3,512,512] f32 tensors,
// smooth-L1 between std maps, global mean.
//
// R3: single fused kernel (last-block reduction), XOR-swizzled smem columns
// for conflict-free LDS.64/STS.64 in all phases, register sliding windows.

#define TILE   32
#define HALO   3
#define HSZ    38                 // TILE + 2*HALO
#define RAWP   41                 // raw pitch in float2
#define HSP    33                 // hsum pitch in float2
#define NINV   (1.0f / 147.0f)    // 1/(C*K*K)
#define EPS    1e-8f
#define HW     (512 * 512)
#define NPIX   (16.0f * 512.0f * 512.0f)
#define NBLK   4096

// Column swizzle: keeps stride-4-float2 group accesses conflict-free.
#define SW(c)  ((c) ^ ((((c) >> 4) << 1)))

__device__ float        g_partials[NBLK];
__device__ unsigned int g_count;   // zero-initialized; self-resets via atomicInc wrap

__global__ __launch_bounds__(256)
void dist_loss_main(const float* __restrict__ pred,
                    const float* __restrict__ tgt,
                    float* __restrict__ out)
{
    __shared__ float2 s_raw[HSZ * RAWP];   // (sum_c x, sum_c x^2), swizzled cols
    __shared__ float2 s_hs [HSZ * HSP];    // horizontal 7-sums, swizzled cols
    __shared__ float  s_red[256];
    __shared__ bool   s_is_last;

    const int tx  = threadIdx.x;           // 0..31
    const int ty  = threadIdx.y;           // 0..7
    const int tid = ty * 32 + tx;
    const int x0  = blockIdx.x * TILE;
    const int y0  = blockIdx.y * TILE;

    const float* base0 = pred + (size_t)blockIdx.z * 3 * HW;
    const float* base1 = tgt  + (size_t)blockIdx.z * 3 * HW;

    float stdv[2][4];

#pragma unroll
    for (int t = 0; t < 2; t++) {
        const float* x = (t == 0) ? base0 : base1;

        // ---- Phase 1: load halo, channel-summed, zero-padded ----
        for (int r = ty; r < HSZ; r += 8) {
            int gy = y0 - HALO + r;
            bool rowok = ((unsigned)gy < 512u);
            const float* rowp = x + gy * 512;
            for (int c = tx; c < HSZ; c += 32) {
                int gx = x0 - HALO + c;
                float s = 0.f, s2 = 0.f;
                if (rowok && ((unsigned)gx < 512u)) {
                    float v0 = rowp[gx];
                    float v1 = rowp[HW + gx];
                    float v2 = rowp[2 * HW + gx];
                    s  = v0 + v1 + v2;
                    s2 = v0 * v0 + v1 * v1 + v2 * v2;
                }
                s_raw[r * RAWP + SW(c)] = make_float2(s, s2);
            }
        }
        __syncthreads();

        // ---- Phase 2: horizontal 7-sum, register sliding window ----
        {
            int g  = tid & 7;        // output cols 4g..4g+3
            int rr = tid >> 3;       // 0..31
#pragma unroll
            for (int rb = 0; rb < HSZ; rb += 32) {
                int r = rb + rr;
                if (r < HSZ) {
                    float2 e[10];
#pragma unroll
                    for (int i = 0; i < 10; i++)
                        e[i] = s_raw[r * RAWP + SW(4 * g + i)];
                    float a = e[0].x + e[1].x + e[2].x + e[3].x + e[4].x + e[5].x + e[6].x;
                    float b = e[0].y + e[1].y + e[2].y + e[3].y + e[4].y + e[5].y + e[6].y;
#pragma unroll
                    for (int q = 0; q < 4; q++) {
                        s_hs[r * HSP + SW(4 * g + q)] = make_float2(a, b);
                        if (q < 3) {
                            a += e[q + 7].x - e[q].x;
                            b += e[q + 7].y - e[q].y;
                        }
                    }
                }
            }
        }
        __syncthreads();

        // ---- Phase 3: vertical 7-sum + std, register sliding window ----
        {
            const int cs = SW(tx);
            float2 v[10];
#pragma unroll
            for (int i = 0; i < 10; i++)
                v[i] = s_hs[(4 * ty + i) * HSP + cs];
            float a = v[0].x + v[1].x + v[2].x + v[3].x + v[4].x + v[5].x + v[6].x;
            float b = v[0].y + v[1].y + v[2].y + v[3].y + v[4].y + v[5].y + v[6].y;
#pragma unroll
            for (int q = 0; q < 4; q++) {
                float mu  = a * NINV;
                float var = b * NINV - mu * mu;
                stdv[t][q] = sqrtf(var + EPS);
                if (q < 3) {
                    a += v[q + 7].x - v[q].x;
                    b += v[q + 7].y - v[q].y;
                }
            }
        }
        __syncthreads();   // smem reused by next tensor
    }

    // ---- smooth-L1 over this thread's 4 pixels ----
    float acc = 0.f;
#pragma unroll
    for (int q = 0; q < 4; q++) {
        float d  = stdv[0][q] - stdv[1][q];
        float ad = fabsf(d);
        acc += (ad < 1.0f) ? 0.5f * d * d : (ad - 0.5f);
    }

    // ---- deterministic block reduction ----
    s_red[tid] = acc;
    __syncthreads();
#pragma unroll
    for (int s = 128; s > 0; s >>= 1) {
        if (tid < s) s_red[tid] += s_red[tid + s];
        __syncthreads();
    }

    const int pidx = blockIdx.z * 256 + blockIdx.y * 16 + blockIdx.x;
    if (tid == 0) {
        g_partials[pidx] = s_red[0];
        __threadfence();
        unsigned int prev = atomicInc(&g_count, NBLK - 1);  // wraps to 0 at NBLK
        s_is_last = (prev == NBLK - 1);
    }
    __syncthreads();

    // ---- last block: final deterministic reduction over all partials ----
    if (s_is_last) {
        float a = 0.f;
#pragma unroll
        for (int i = 0; i < NBLK / 256; i++)
            a += g_partials[tid + i * 256];
        s_red[tid] = a;
        __syncthreads();
#pragma unroll
        for (int s = 128; s > 0; s >>= 1) {
            if (tid < s) s_red[tid] += s_red[tid + s];
            __syncthreads();
        }
        if (tid == 0) out[0] = s_red[0] * (1.0f / NPIX);
    }
}

extern "C" void kernel_launch(void* const* d_in, const int* in_sizes, int n_in,
                              void* d_out, int out_size)
{
    const float* pred = (const float*)d_in[0];
    const float* tgt  = (const float*)d_in[1];
    float* out = (float*)d_out;

    dim3 grid(16, 16, 16);
    dim3 block(32, 8);
    dist_loss_main<<<grid, block>>>(pred, tgt, out);
}

// round 4
// speedup vs baseline: 1.5265x; 1.2860x over previous
#include <cuda_runtime.h>
#include <math.h>

// DistributionLoss: local 7x7x3 std of two [16,3,512,512] f32 tensors,
// smooth-L1 between std maps, global mean.
//
// R4: instruction-count attack (kernel is issue/latency bound, ALU=42% was
// addressing). LDG.128 loads, both tensors fused into float4 smem entries
// (halves LDS/STS instr + syncs), 6-register sliding windows, hoisted
// swizzled offsets, fused last-block reduction.

#define TILE 32
#define HALO 3
#define HSZ  38
#define RAWP 41                 // pitch in float4
#define HSP  33                 // pitch in float4
#define NINV (1.0f / 147.0f)
#define EPS  1e-8f
#define HW   (512 * 512)
#define NPIX (16.0f * 512.0f * 512.0f)
#define NBLK 4096

// float4-granularity swizzle: distinct-mod-8 for stride-4 group access.
#define SW4(c) ((c) ^ (((c) >> 3) & 3))

__device__ float        g_partials[NBLK];
__device__ unsigned int g_count;   // zero-init; self-resets via atomicInc wrap

__global__ __launch_bounds__(256, 4)
void dist_loss_main(const float* __restrict__ pred,
                    const float* __restrict__ tgt,
                    float* __restrict__ out)
{
    __shared__ float4 s_raw[HSZ * RAWP];   // (s_p, s2_p, s_t, s2_t)
    __shared__ float4 s_hs [HSZ * HSP];    // horizontal 7-sums
    __shared__ float  s_red[256];
    __shared__ bool   s_is_last;

    const int tx  = threadIdx.x;           // 0..31
    const int ty  = threadIdx.y;           // 0..7
    const int tid = ty * 32 + tx;
    const int x0  = blockIdx.x * TILE;
    const int y0  = blockIdx.y * TILE;

    const float* p  = pred + (size_t)blockIdx.z * 3 * HW;
    const float* tg = tgt  + (size_t)blockIdx.z * 3 * HW;

    // ---- Phase 1: 380 tasks = 38 rows x 10 col-groups of 4 floats ----
    // Loads the 40-wide aligned segment [x0-4, x0+36), stores halo cols 0..37.
    for (int task = tid; task < 380; task += 256) {
        int r   = task / 10;
        int g   = task - r * 10;
        int gy  = y0 - HALO + r;
        int gx0 = x0 - 4 + 4 * g;
        bool rowok = ((unsigned)gy < 512u);

        float sp[4], p2[4], st[4], t2[4];
        if (rowok && gx0 >= 0 && gx0 <= 508) {
            size_t off = (size_t)gy * 512 + gx0;
            float4 a0 = *(const float4*)(p  + off);
            float4 a1 = *(const float4*)(p  + HW + off);
            float4 a2 = *(const float4*)(p  + 2 * HW + off);
            float4 b0 = *(const float4*)(tg + off);
            float4 b1 = *(const float4*)(tg + HW + off);
            float4 b2 = *(const float4*)(tg + 2 * HW + off);
            sp[0] = a0.x + a1.x + a2.x;  p2[0] = a0.x*a0.x + a1.x*a1.x + a2.x*a2.x;
            sp[1] = a0.y + a1.y + a2.y;  p2[1] = a0.y*a0.y + a1.y*a1.y + a2.y*a2.y;
            sp[2] = a0.z + a1.z + a2.z;  p2[2] = a0.z*a0.z + a1.z*a1.z + a2.z*a2.z;
            sp[3] = a0.w + a1.w + a2.w;  p2[3] = a0.w*a0.w + a1.w*a1.w + a2.w*a2.w;
            st[0] = b0.x + b1.x + b2.x;  t2[0] = b0.x*b0.x + b1.x*b1.x + b2.x*b2.x;
            st[1] = b0.y + b1.y + b2.y;  t2[1] = b0.y*b0.y + b1.y*b1.y + b2.y*b2.y;
            st[2] = b0.z + b1.z + b2.z;  t2[2] = b0.z*b0.z + b1.z*b1.z + b2.z*b2.z;
            st[3] = b0.w + b1.w + b2.w;  t2[3] = b0.w*b0.w + b1.w*b1.w + b2.w*b2.w;
        } else {
            // rare path: boundary rows / edge-x blocks, per-element guarded
#pragma unroll
            for (int j = 0; j < 4; j++) {
                int gx = gx0 + j;
                float v0 = 0.f, v1 = 0.f, v2 = 0.f;
                float w0 = 0.f, w1 = 0.f, w2 = 0.f;
                if (rowok && ((unsigned)gx < 512u)) {
                    size_t off = (size_t)gy * 512 + gx;
                    v0 = p[off];  v1 = p[HW + off];  v2 = p[2 * HW + off];
                    w0 = tg[off]; w1 = tg[HW + off]; w2 = tg[2 * HW + off];
                }
                sp[j] = v0 + v1 + v2;  p2[j] = v0*v0 + v1*v1 + v2*v2;
                st[j] = w0 + w1 + w2;  t2[j] = w0*w0 + w1*w1 + w2*w2;
            }
        }
#pragma unroll
        for (int j = 0; j < 4; j++) {
            int c = 4 * g + j - 1;
            if ((unsigned)c < (unsigned)HSZ)
                s_raw[r * RAWP + SW4(c)] = make_float4(sp[j], p2[j], st[j], t2[j]);
        }
    }
    __syncthreads();

    // ---- Phase 2: horizontal 7-sum, sliding window (both tensors) ----
    {
        const int g  = tid & 7;        // output cols 4g..4g+3
        const int rr = tid >> 3;       // 0..31
        // hoist swizzled offsets (r-independent)
        int o[10];
#pragma unroll
        for (int i = 0; i < 10; i++) o[i] = SW4(4 * g + i);

#pragma unroll
        for (int rb = 0; rb < HSZ; rb += 32) {
            int r = rb + rr;
            if (r < HSZ) {
                const float4* row = s_raw + r * RAWP;
                float4* hrow = s_hs + r * HSP;
                float4 e0 = row[o[0]], e1 = row[o[1]], e2 = row[o[2]];
                float4 e3 = row[o[3]], e4 = row[o[4]], e5 = row[o[5]], e6 = row[o[6]];
                float ap = e0.x + e1.x + e2.x + e3.x + e4.x + e5.x + e6.x;
                float bp = e0.y + e1.y + e2.y + e3.y + e4.y + e5.y + e6.y;
                float a_t = e0.z + e1.z + e2.z + e3.z + e4.z + e5.z + e6.z;
                float bt = e0.w + e1.w + e2.w + e3.w + e4.w + e5.w + e6.w;
                float4 e7 = row[o[7]], e8 = row[o[8]], e9 = row[o[9]];

                hrow[o[0]] = make_float4(ap, bp, a_t, bt);
                ap += e7.x - e0.x; bp += e7.y - e0.y; a_t += e7.z - e0.z; bt += e7.w - e0.w;
                hrow[o[1]] = make_float4(ap, bp, a_t, bt);
                ap += e8.x - e1.x; bp += e8.y - e1.y; a_t += e8.z - e1.z; bt += e8.w - e1.w;
                hrow[o[2]] = make_float4(ap, bp, a_t, bt);
                ap += e9.x - e2.x; bp += e9.y - e2.y; a_t += e9.z - e2.z; bt += e9.w - e2.w;
                hrow[o[3]] = make_float4(ap, bp, a_t, bt);
            }
        }
    }
    __syncthreads();

    // ---- Phase 3: vertical 7-sum + std + smooth-L1, sliding window ----
    float acc = 0.f;
    {
        const int cs = SW4(tx);
        const float4* col = s_hs + cs;
        const int rbase = 4 * ty;
        float4 v0 = col[(rbase + 0) * HSP], v1 = col[(rbase + 1) * HSP], v2 = col[(rbase + 2) * HSP];
        float4 v3 = col[(rbase + 3) * HSP], v4 = col[(rbase + 4) * HSP];
        float4 v5 = col[(rbase + 5) * HSP], v6 = col[(rbase + 6) * HSP];
        float ap = v0.x + v1.x + v2.x + v3.x + v4.x + v5.x + v6.x;
        float bp = v0.y + v1.y + v2.y + v3.y + v4.y + v5.y + v6.y;
        float a_t = v0.z + v1.z + v2.z + v3.z + v4.z + v5.z + v6.z;
        float bt = v0.w + v1.w + v2.w + v3.w + v4.w + v5.w + v6.w;
        float4 v7 = col[(rbase + 7) * HSP], v8 = col[(rbase + 8) * HSP], v9 = col[(rbase + 9) * HSP];

#pragma unroll
        for (int q = 0; q < 4; q++) {
            float mup  = ap * NINV;
            float varp = bp * NINV - mup * mup;
            float sdp  = sqrtf(varp + EPS);
            float mut  = a_t * NINV;
            float vart = bt * NINV - mut * mut;
            float sdt  = sqrtf(vart + EPS);
            float d  = sdp - sdt;
            float ad = fabsf(d);
            acc += (ad < 1.0f) ? 0.5f * d * d : (ad - 0.5f);
            if (q == 0) { ap += v7.x - v0.x; bp += v7.y - v0.y; a_t += v7.z - v0.z; bt += v7.w - v0.w; }
            if (q == 1) { ap += v8.x - v1.x; bp += v8.y - v1.y; a_t += v8.z - v1.z; bt += v8.w - v1.w; }
            if (q == 2) { ap += v9.x - v2.x; bp += v9.y - v2.y; a_t += v9.z - v2.z; bt += v9.w - v2.w; }
        }
    }

    // ---- deterministic block reduction ----
    s_red[tid] = acc;
    __syncthreads();
#pragma unroll
    for (int s = 128; s > 0; s >>= 1) {
        if (tid < s) s_red[tid] += s_red[tid + s];
        __syncthreads();
    }

    const int pidx = blockIdx.z * 256 + blockIdx.y * 16 + blockIdx.x;
    if (tid == 0) {
        g_partials[pidx] = s_red[0];
        __threadfence();
        unsigned int prev = atomicInc(&g_count, NBLK - 1);  // wraps to 0 at NBLK
        s_is_last = (prev == NBLK - 1);
    }
    __syncthreads();

    // ---- last block: final deterministic reduction ----
    if (s_is_last) {
        float a = 0.f;
#pragma unroll
        for (int i = 0; i < NBLK / 256; i++)
            a += g_partials[tid + i * 256];
        s_red[tid] = a;
        __syncthreads();
#pragma unroll
        for (int s = 128; s > 0; s >>= 1) {
            if (tid < s) s_red[tid] += s_red[tid + s];
            __syncthreads();
        }
        if (tid == 0) out[0] = s_red[0] * (1.0f / NPIX);
    }
}

extern "C" void kernel_launch(void* const* d_in, const int* in_sizes, int n_in,
                              void* d_out, int out_size)
{
    const float* pred = (const float*)d_in[0];
    const float* tgt  = (const float*)d_in[1];
    float* out = (float*)d_out;

    dim3 grid(16, 16, 16);
    dim3 block(32, 8);
    dist_loss_main<<<grid, block>>>(pred, tgt, out);
}

// round 5
// speedup vs baseline: 1.5705x; 1.0288x over previous
#include <cuda_runtime.h>
#include <math.h>

// DistributionLoss: local 7x7x3 std of two [16,3,512,512] f32 tensors,
// smooth-L1 between std maps, global mean.
//
// R5: 64x32 tile, single smem buffer (phase-2 horizontal sums computed
// IN-PLACE over the raw buffer, row-disjoint passes), 8-row phase-3 strips
// (1.75 LDS.128/output), 5 blocks/SM via launch_bounds(256,5).

#define TW   64
#define TH   32
#define HALO 3
#define HR   38                  // halo rows
#define WC   70                  // halo cols
#define PITCH 70                 // smem pitch in float4
#define NINV (1.0f / 147.0f)
#define EPS  1e-8f
#define HWSZ (512 * 512)
#define NPIX (16.0f * 512.0f * 512.0f)
#define NBLK 2048

#define SW4(c) ((c) ^ (((c) >> 3) & 3))

__device__ float        g_partials[NBLK];
__device__ unsigned int g_count;   // zero-init; self-resets via atomicInc wrap

__device__ __forceinline__ float4 f4add(float4 a, float4 b) {
    return make_float4(a.x + b.x, a.y + b.y, a.z + b.z, a.w + b.w);
}
__device__ __forceinline__ float4 f4sub(float4 a, float4 b) {
    return make_float4(a.x - b.x, a.y - b.y, a.z - b.z, a.w - b.w);
}

__global__ __launch_bounds__(256, 5)
void dist_loss_main(const float* __restrict__ pred,
                    const float* __restrict__ tgt,
                    float* __restrict__ out)
{
    __shared__ float4 s_raw[HR * PITCH];   // (s_p, s2_p, s_t, s2_t); later hsums at cols 0..63
    __shared__ float  s_red[256];
    __shared__ bool   s_is_last;

    const int tid = threadIdx.y * 32 + threadIdx.x;
    const int x0  = blockIdx.x * TW;
    const int y0  = blockIdx.y * TH;

    const float* p  = pred + (size_t)blockIdx.z * 3 * HWSZ;
    const float* tg = tgt  + (size_t)blockIdx.z * 3 * HWSZ;

    // ---- Phase 1: 684 tasks = 38 rows x 18 float4 col-groups ----
    // Covers aligned segment [x0-4, x0+68); stores halo cols 0..69.
    for (int task = tid; task < HR * 18; task += 256) {
        int r   = task / 18;
        int g   = task - r * 18;
        int gy  = y0 - HALO + r;
        int gx0 = x0 - 4 + 4 * g;
        bool rowok = ((unsigned)gy < 512u);

        float sp[4], p2[4], st[4], t2[4];
        if (rowok && gx0 >= 0 && gx0 <= 508) {
            size_t off = (size_t)gy * 512 + gx0;
            float4 a0 = *(const float4*)(p  + off);
            float4 a1 = *(const float4*)(p  + HWSZ + off);
            float4 a2 = *(const float4*)(p  + 2 * HWSZ + off);
            float4 b0 = *(const float4*)(tg + off);
            float4 b1 = *(const float4*)(tg + HWSZ + off);
            float4 b2 = *(const float4*)(tg + 2 * HWSZ + off);
            sp[0] = a0.x + a1.x + a2.x;  p2[0] = a0.x*a0.x + a1.x*a1.x + a2.x*a2.x;
            sp[1] = a0.y + a1.y + a2.y;  p2[1] = a0.y*a0.y + a1.y*a1.y + a2.y*a2.y;
            sp[2] = a0.z + a1.z + a2.z;  p2[2] = a0.z*a0.z + a1.z*a1.z + a2.z*a2.z;
            sp[3] = a0.w + a1.w + a2.w;  p2[3] = a0.w*a0.w + a1.w*a1.w + a2.w*a2.w;
            st[0] = b0.x + b1.x + b2.x;  t2[0] = b0.x*b0.x + b1.x*b1.x + b2.x*b2.x;
            st[1] = b0.y + b1.y + b2.y;  t2[1] = b0.y*b0.y + b1.y*b1.y + b2.y*b2.y;
            st[2] = b0.z + b1.z + b2.z;  t2[2] = b0.z*b0.z + b1.z*b1.z + b2.z*b2.z;
            st[3] = b0.w + b1.w + b2.w;  t2[3] = b0.w*b0.w + b1.w*b1.w + b2.w*b2.w;
        } else {
#pragma unroll
            for (int j = 0; j < 4; j++) {
                int gx = gx0 + j;
                float v0 = 0.f, v1 = 0.f, v2 = 0.f;
                float w0 = 0.f, w1 = 0.f, w2 = 0.f;
                if (rowok && ((unsigned)gx < 512u)) {
                    size_t off = (size_t)gy * 512 + gx;
                    v0 = p[off];  v1 = p[HWSZ + off];  v2 = p[2 * HWSZ + off];
                    w0 = tg[off]; w1 = tg[HWSZ + off]; w2 = tg[2 * HWSZ + off];
                }
                sp[j] = v0 + v1 + v2;  p2[j] = v0*v0 + v1*v1 + v2*v2;
                st[j] = w0 + w1 + w2;  t2[j] = w0*w0 + w1*w1 + w2*w2;
            }
        }
#pragma unroll
        for (int j = 0; j < 4; j++) {
            int c = 4 * g + j - 1;
            if ((unsigned)c < (unsigned)WC)
                s_raw[r * PITCH + SW4(c)] = make_float4(sp[j], p2[j], st[j], t2[j]);
        }
    }
    __syncthreads();

    // ---- Phase 2: horizontal 7-sum IN PLACE, row-disjoint passes ----
    // 608 tasks = 38 rows x 16 groups; pass p handles rows 16p..16p+15.
    // Per pass: load full 10-strip -> sync -> overwrite cols 4g..4g+3.
    {
        const int g2 = tid & 15;     // output cols 4*g2 .. 4*g2+3
        const int r2 = tid >> 4;     // 0..15
        int o[10];
#pragma unroll
        for (int i = 0; i < 10; i++) o[i] = SW4(4 * g2 + i);

#pragma unroll
        for (int pss = 0; pss < 3; pss++) {
            int r = pss * 16 + r2;
            bool active = (r < HR);
            float4 h0, h1, h2, h3;
            if (active) {
                const float4* row = s_raw + r * PITCH;
                float4 e0 = row[o[0]], e1 = row[o[1]], e2 = row[o[2]];
                float4 e3 = row[o[3]], e4 = row[o[4]], e5 = row[o[5]], e6 = row[o[6]];
                float4 e7 = row[o[7]], e8 = row[o[8]], e9 = row[o[9]];
                h0 = f4add(f4add(f4add(e0, e1), f4add(e2, e3)),
                           f4add(f4add(e4, e5), e6));
                h1 = f4add(h0, f4sub(e7, e0));
                h2 = f4add(h1, f4sub(e8, e1));
                h3 = f4add(h2, f4sub(e9, e2));
            }
            __syncthreads();
            if (active) {
                float4* row = s_raw + r * PITCH;
                row[o[0]] = h0;
                row[o[1]] = h1;
                row[o[2]] = h2;
                row[o[3]] = h3;
            }
        }
    }
    __syncthreads();

    // ---- Phase 3: vertical 7-sum + std + smooth-L1; 8-row strips ----
    float acc = 0.f;
    {
        const int c3 = tid & 63;     // output col 0..63
        const int rg = tid >> 6;     // 0..3 -> output rows 8rg..8rg+7
        const float4* col = s_raw + SW4(c3);
        const int rb = rg * 8;

        float4 v[14];
#pragma unroll
        for (int i = 0; i < 7; i++) v[i] = col[(rb + i) * PITCH];
        float4 w = f4add(f4add(f4add(v[0], v[1]), f4add(v[2], v[3])),
                         f4add(f4add(v[4], v[5]), v[6]));
#pragma unroll
        for (int q = 0; q < 8; q++) {
            float mup  = w.x * NINV;
            float varp = w.y * NINV - mup * mup;
            float sdp  = sqrtf(varp + EPS);
            float mut  = w.z * NINV;
            float vart = w.w * NINV - mut * mut;
            float sdt  = sqrtf(vart + EPS);
            float d  = sdp - sdt;
            float ad = fabsf(d);
            acc += (ad < 1.0f) ? 0.5f * d * d : (ad - 0.5f);
            if (q < 7) {
                v[7 + q] = col[(rb + 7 + q) * PITCH];
                w = f4add(w, f4sub(v[7 + q], v[q]));
            }
        }
    }

    // ---- deterministic block reduction ----
    s_red[tid] = acc;
    __syncthreads();
#pragma unroll
    for (int s = 128; s > 0; s >>= 1) {
        if (tid < s) s_red[tid] += s_red[tid + s];
        __syncthreads();
    }

    const int pidx = blockIdx.z * 128 + blockIdx.y * 8 + blockIdx.x;
    if (tid == 0) {
        g_partials[pidx] = s_red[0];
        __threadfence();
        unsigned int prev = atomicInc(&g_count, NBLK - 1);  // wraps to 0 at NBLK
        s_is_last = (prev == NBLK - 1);
    }
    __syncthreads();

    // ---- last block: final deterministic reduction ----
    if (s_is_last) {
        float a = 0.f;
#pragma unroll
        for (int i = 0; i < NBLK / 256; i++)
            a += g_partials[tid + i * 256];
        s_red[tid] = a;
        __syncthreads();
#pragma unroll
        for (int s = 128; s > 0; s >>= 1) {
            if (tid < s) s_red[tid] += s_red[tid + s];
            __syncthreads();
        }
        if (tid == 0) out[0] = s_red[0] * (1.0f / NPIX);
    }
}

extern "C" void kernel_launch(void* const* d_in, const int* in_sizes, int n_in,
                              void* d_out, int out_size)
{
    const float* pred = (const float*)d_in[0];
    const float* tgt  = (const float*)d_in[1];
    float* out = (float*)d_out;

    dim3 grid(8, 16, 16);   // x tiles (64 wide), y tiles (32 tall), batch
    dim3 block(32, 8);
    dist_loss_main<<<grid, block>>>(pred, tgt, out);
}

// round 6
// speedup vs baseline: 1.8919x; 1.2046x over previous
#include <cuda_runtime.h>
#include <math.h>

// DistributionLoss: local 7x7x3 std of two [16,3,512,512] f32 tensors,
// smooth-L1 between std maps, global mean.
//
// R6: stall-bound attack. 64x16 tile (24.7 KB smem), launch_bounds(256,6)
// -> 6 blocks/SM (75% occ ceiling). In-place horizontal pass (2 passes),
// shuffle-based reductions, 6 barriers/block total.

#define TW   64
#define TH   16
#define HALO 3
#define HR   22                  // halo rows  (TH + 6)
#define WC   70                  // halo cols  (TW + 6)
#define PITCH 70                 // smem pitch in float4
#define NINV (1.0f / 147.0f)
#define EPS  1e-8f
#define HWSZ (512 * 512)
#define NPIX (16.0f * 512.0f * 512.0f)
#define NBLK 4096                // 8 x 32 x 16

#define SW4(c) ((c) ^ (((c) >> 3) & 3))

__device__ float        g_partials[NBLK];
__device__ unsigned int g_count;   // zero-init; self-resets via atomicInc wrap

__device__ __forceinline__ float4 f4add(float4 a, float4 b) {
    return make_float4(a.x + b.x, a.y + b.y, a.z + b.z, a.w + b.w);
}
__device__ __forceinline__ float4 f4sub(float4 a, float4 b) {
    return make_float4(a.x - b.x, a.y - b.y, a.z - b.z, a.w - b.w);
}

__global__ __launch_bounds__(256, 6)
void dist_loss_main(const float* __restrict__ pred,
                    const float* __restrict__ tgt,
                    float* __restrict__ out)
{
    __shared__ float4 s_raw[HR * PITCH];   // (s_p, s2_p, s_t, s2_t); hsums in-place later
    __shared__ float  s_warp[8];
    __shared__ bool   s_is_last;

    const int tid  = threadIdx.y * 32 + threadIdx.x;
    const int lane = threadIdx.x;
    const int wid  = threadIdx.y;
    const int x0   = blockIdx.x * TW;
    const int y0   = blockIdx.y * TH;

    const float* p  = pred + (size_t)blockIdx.z * 3 * HWSZ;
    const float* tg = tgt  + (size_t)blockIdx.z * 3 * HWSZ;

    // ---- Phase 1: 396 tasks = 22 rows x 18 float4 col-groups ----
    // Covers aligned segment [x0-4, x0+68); stores halo cols 0..69.
    for (int task = tid; task < HR * 18; task += 256) {
        int r   = task / 18;
        int g   = task - r * 18;
        int gy  = y0 - HALO + r;
        int gx0 = x0 - 4 + 4 * g;
        bool rowok = ((unsigned)gy < 512u);

        float sp[4], p2[4], st[4], t2[4];
        if (rowok && gx0 >= 0 && gx0 <= 508) {
            size_t off = (size_t)gy * 512 + gx0;
            float4 a0 = *(const float4*)(p  + off);
            float4 a1 = *(const float4*)(p  + HWSZ + off);
            float4 a2 = *(const float4*)(p  + 2 * HWSZ + off);
            float4 b0 = *(const float4*)(tg + off);
            float4 b1 = *(const float4*)(tg + HWSZ + off);
            float4 b2 = *(const float4*)(tg + 2 * HWSZ + off);
            sp[0] = a0.x + a1.x + a2.x;  p2[0] = a0.x*a0.x + a1.x*a1.x + a2.x*a2.x;
            sp[1] = a0.y + a1.y + a2.y;  p2[1] = a0.y*a0.y + a1.y*a1.y + a2.y*a2.y;
            sp[2] = a0.z + a1.z + a2.z;  p2[2] = a0.z*a0.z + a1.z*a1.z + a2.z*a2.z;
            sp[3] = a0.w + a1.w + a2.w;  p2[3] = a0.w*a0.w + a1.w*a1.w + a2.w*a2.w;
            st[0] = b0.x + b1.x + b2.x;  t2[0] = b0.x*b0.x + b1.x*b1.x + b2.x*b2.x;
            st[1] = b0.y + b1.y + b2.y;  t2[1] = b0.y*b0.y + b1.y*b1.y + b2.y*b2.y;
            st[2] = b0.z + b1.z + b2.z;  t2[2] = b0.z*b0.z + b1.z*b1.z + b2.z*b2.z;
            st[3] = b0.w + b1.w + b2.w;  t2[3] = b0.w*b0.w + b1.w*b1.w + b2.w*b2.w;
        } else {
#pragma unroll
            for (int j = 0; j < 4; j++) {
                int gx = gx0 + j;
                float v0 = 0.f, v1 = 0.f, v2 = 0.f;
                float w0 = 0.f, w1 = 0.f, w2 = 0.f;
                if (rowok && ((unsigned)gx < 512u)) {
                    size_t off = (size_t)gy * 512 + gx;
                    v0 = p[off];  v1 = p[HWSZ + off];  v2 = p[2 * HWSZ + off];
                    w0 = tg[off]; w1 = tg[HWSZ + off]; w2 = tg[2 * HWSZ + off];
                }
                sp[j] = v0 + v1 + v2;  p2[j] = v0*v0 + v1*v1 + v2*v2;
                st[j] = w0 + w1 + w2;  t2[j] = w0*w0 + w1*w1 + w2*w2;
            }
        }
#pragma unroll
        for (int j = 0; j < 4; j++) {
            int c = 4 * g + j - 1;
            if ((unsigned)c < (unsigned)WC)
                s_raw[r * PITCH + SW4(c)] = make_float4(sp[j], p2[j], st[j], t2[j]);
        }
    }
    __syncthreads();                                           // B1

    // ---- Phase 2: horizontal 7-sum IN PLACE ----
    // 352 tasks = 22 rows x 16 groups; pass 0: rows 0-15 (all 256 threads),
    // pass 1: rows 16-21 (96 threads). Passes are row-disjoint -> no
    // inter-pass barrier; each pass needs load->sync->store.
    {
        const int g2 = tid & 15;     // output cols 4*g2 .. 4*g2+3
        const int r2 = tid >> 4;     // 0..15
        int o[10];
#pragma unroll
        for (int i = 0; i < 10; i++) o[i] = SW4(4 * g2 + i);

#pragma unroll
        for (int pss = 0; pss < 2; pss++) {
            int r = pss * 16 + r2;
            bool active = (r < HR);
            float4 h0, h1, h2, h3;
            if (active) {
                const float4* row = s_raw + r * PITCH;
                float4 e0 = row[o[0]], e1 = row[o[1]], e2 = row[o[2]];
                float4 e3 = row[o[3]], e4 = row[o[4]], e5 = row[o[5]], e6 = row[o[6]];
                float4 e7 = row[o[7]], e8 = row[o[8]], e9 = row[o[9]];
                h0 = f4add(f4add(f4add(e0, e1), f4add(e2, e3)),
                           f4add(f4add(e4, e5), e6));
                h1 = f4add(h0, f4sub(e7, e0));
                h2 = f4add(h1, f4sub(e8, e1));
                h3 = f4add(h2, f4sub(e9, e2));
            }
            __syncthreads();                                   // B2 / B3
            if (active) {
                float4* row = s_raw + r * PITCH;
                row[o[0]] = h0;
                row[o[1]] = h1;
                row[o[2]] = h2;
                row[o[3]] = h3;
            }
        }
    }
    __syncthreads();                                           // B4

    // ---- Phase 3: vertical 7-sum + std + smooth-L1; 4-row strips ----
    float acc = 0.f;
    {
        const int c3 = tid & 63;     // output col 0..63
        const int rg = tid >> 6;     // 0..3 -> output rows 4rg..4rg+3
        const float4* col = s_raw + SW4(c3);
        const int rb = rg * 4;

        float4 v[10];
#pragma unroll
        for (int i = 0; i < 7; i++) v[i] = col[(rb + i) * PITCH];
        float4 w = f4add(f4add(f4add(v[0], v[1]), f4add(v[2], v[3])),
                         f4add(f4add(v[4], v[5]), v[6]));
#pragma unroll
        for (int q = 0; q < 4; q++) {
            float mup  = w.x * NINV;
            float varp = w.y * NINV - mup * mup;
            float sdp  = sqrtf(varp + EPS);
            float mut  = w.z * NINV;
            float vart = w.w * NINV - mut * mut;
            float sdt  = sqrtf(vart + EPS);
            float d  = sdp - sdt;
            float ad = fabsf(d);
            acc += (ad < 1.0f) ? 0.5f * d * d : (ad - 0.5f);
            if (q < 3) {
                v[7 + q] = col[(rb + 7 + q) * PITCH];
                w = f4add(w, f4sub(v[7 + q], v[q]));
            }
        }
    }

    // ---- block reduction: warp shuffle + one barrier ----
#pragma unroll
    for (int off = 16; off > 0; off >>= 1)
        acc += __shfl_down_sync(0xffffffffu, acc, off);
    if (lane == 0) s_warp[wid] = acc;
    __syncthreads();                                           // B5

    const int pidx = blockIdx.z * 256 + blockIdx.y * 8 + blockIdx.x;
    if (wid == 0) {
        float a = (lane < 8) ? s_warp[lane] : 0.f;
#pragma unroll
        for (int off = 4; off > 0; off >>= 1)
            a += __shfl_down_sync(0xffffffffu, a, off);
        if (lane == 0) {
            g_partials[pidx] = a;
            __threadfence();
            unsigned int prev = atomicInc(&g_count, NBLK - 1);  // wraps to 0
            s_is_last = (prev == NBLK - 1);
        }
    }
    __syncthreads();                                           // B6

    // ---- last block: final deterministic reduction ----
    if (s_is_last) {
        float a = 0.f;
#pragma unroll
        for (int i = 0; i < NBLK / 256; i++)
            a += g_partials[tid + i * 256];
#pragma unroll
        for (int off = 16; off > 0; off >>= 1)
            a += __shfl_down_sync(0xffffffffu, a, off);
        if (lane == 0) s_warp[wid] = a;
        __syncthreads();
        if (tid == 0) {
            float s = 0.f;
#pragma unroll
            for (int i = 0; i < 8; i++) s += s_warp[i];
            out[0] = s * (1.0f / NPIX);
        }
    }
}

extern "C" void kernel_launch(void* const* d_in, const int* in_sizes, int n_in,
                              void* d_out, int out_size)
{
    const float* pred = (const float*)d_in[0];
    const float* tgt  = (const float*)d_in[1];
    float* out = (float*)d_out;

    dim3 grid(8, 32, 16);   // x tiles (64 wide), y tiles (16 tall), batch
    dim3 block(32, 8);
    dist_loss_main<<<grid, block>>>(pred, tgt, out);
}

// round 7
// speedup vs baseline: 1.9903x; 1.0520x over previous
#include <cuda_runtime.h>
#include <cuda_fp16.h>
#include <math.h>

// DistributionLoss: local 7x7x3 std of two [16,3,512,512] f32 tensors,
// smooth-L1 between std maps, global mean.
//
// R7: L1-bound attack. Smem intermediates in fp16: 8-byte cells
// (half2(s,s2)_pred, half2(s,s2)_tgt) -> smem bytes halved; sliding box
// sums in half2 SIMD (hadd2/hsub2) -> fewer issue slots. fp32 only at the
// final variance/sqrt. Error budget ~1e-4 << 1e-3 gate.

#define TW    64
#define TH    16
#define HALO  3
#define HR    22                  // halo rows  (TH + 6)
#define WC    70                  // halo cols  (TW + 6)
#define PITCH 74                  // smem pitch in 8B cells (max swizzled 73)
#define NINV  (1.0f / 147.0f)
#define EPS   1e-8f
#define HWSZ  (512 * 512)
#define NPIX  (16.0f * 512.0f * 512.0f)
#define NBLK  4096                // 8 x 32 x 16

// 8B-cell swizzle: injective, distinct mod 16 for stride-4 and stride-1.
#define SWC(c) ((c) + ((c) >> 4))

__device__ float        g_partials[NBLK];
__device__ unsigned int g_count;   // zero-init; self-resets via atomicInc wrap

struct Cell { __half2 p, t; };     // (s, s2) for pred / tgt

__device__ __forceinline__ Cell u2c(uint2 v) {
    Cell c;
    c.p = *reinterpret_cast<__half2*>(&v.x);
    c.t = *reinterpret_cast<__half2*>(&v.y);
    return c;
}
__device__ __forceinline__ uint2 c2u(Cell c) {
    uint2 v;
    v.x = *reinterpret_cast<unsigned int*>(&c.p);
    v.y = *reinterpret_cast<unsigned int*>(&c.t);
    return v;
}
__device__ __forceinline__ Cell cadd(Cell a, Cell b) {
    Cell r; r.p = __hadd2(a.p, b.p); r.t = __hadd2(a.t, b.t); return r;
}
__device__ __forceinline__ Cell cslide(Cell w, Cell in, Cell out) {
    Cell r;
    r.p = __hadd2(w.p, __hsub2(in.p, out.p));
    r.t = __hadd2(w.t, __hsub2(in.t, out.t));
    return r;
}

__global__ __launch_bounds__(256, 6)
void dist_loss_main(const float* __restrict__ pred,
                    const float* __restrict__ tgt,
                    float* __restrict__ out)
{
    __shared__ uint2 s_raw[HR * PITCH];   // 8B cells; hsums in-place later
    __shared__ float s_warp[8];
    __shared__ bool  s_is_last;

    const int tid  = threadIdx.y * 32 + threadIdx.x;
    const int lane = threadIdx.x;
    const int wid  = threadIdx.y;
    const int x0   = blockIdx.x * TW;
    const int y0   = blockIdx.y * TH;

    const float* p  = pred + (size_t)blockIdx.z * 3 * HWSZ;
    const float* tg = tgt  + (size_t)blockIdx.z * 3 * HWSZ;

    // ---- Phase 1: 396 tasks = 22 rows x 18 float4 col-groups ----
    for (int task = tid; task < HR * 18; task += 256) {
        int r   = task / 18;
        int g   = task - r * 18;
        int gy  = y0 - HALO + r;
        int gx0 = x0 - 4 + 4 * g;
        bool rowok = ((unsigned)gy < 512u);

        float sp[4], p2[4], st[4], t2[4];
        if (rowok && gx0 >= 0 && gx0 <= 508) {
            size_t off = (size_t)gy * 512 + gx0;
            float4 a0 = *(const float4*)(p  + off);
            float4 a1 = *(const float4*)(p  + HWSZ + off);
            float4 a2 = *(const float4*)(p  + 2 * HWSZ + off);
            float4 b0 = *(const float4*)(tg + off);
            float4 b1 = *(const float4*)(tg + HWSZ + off);
            float4 b2 = *(const float4*)(tg + 2 * HWSZ + off);
            sp[0] = a0.x + a1.x + a2.x;  p2[0] = a0.x*a0.x + a1.x*a1.x + a2.x*a2.x;
            sp[1] = a0.y + a1.y + a2.y;  p2[1] = a0.y*a0.y + a1.y*a1.y + a2.y*a2.y;
            sp[2] = a0.z + a1.z + a2.z;  p2[2] = a0.z*a0.z + a1.z*a1.z + a2.z*a2.z;
            sp[3] = a0.w + a1.w + a2.w;  p2[3] = a0.w*a0.w + a1.w*a1.w + a2.w*a2.w;
            st[0] = b0.x + b1.x + b2.x;  t2[0] = b0.x*b0.x + b1.x*b1.x + b2.x*b2.x;
            st[1] = b0.y + b1.y + b2.y;  t2[1] = b0.y*b0.y + b1.y*b1.y + b2.y*b2.y;
            st[2] = b0.z + b1.z + b2.z;  t2[2] = b0.z*b0.z + b1.z*b1.z + b2.z*b2.z;
            st[3] = b0.w + b1.w + b2.w;  t2[3] = b0.w*b0.w + b1.w*b1.w + b2.w*b2.w;
        } else {
#pragma unroll
            for (int j = 0; j < 4; j++) {
                int gx = gx0 + j;
                float v0 = 0.f, v1 = 0.f, v2 = 0.f;
                float w0 = 0.f, w1 = 0.f, w2 = 0.f;
                if (rowok && ((unsigned)gx < 512u)) {
                    size_t off = (size_t)gy * 512 + gx;
                    v0 = p[off];  v1 = p[HWSZ + off];  v2 = p[2 * HWSZ + off];
                    w0 = tg[off]; w1 = tg[HWSZ + off]; w2 = tg[2 * HWSZ + off];
                }
                sp[j] = v0 + v1 + v2;  p2[j] = v0*v0 + v1*v1 + v2*v2;
                st[j] = w0 + w1 + w2;  t2[j] = w0*w0 + w1*w1 + w2*w2;
            }
        }
#pragma unroll
        for (int j = 0; j < 4; j++) {
            int c = 4 * g + j - 1;
            if ((unsigned)c < (unsigned)WC) {
                Cell cl;
                cl.p = __floats2half2_rn(sp[j], p2[j]);
                cl.t = __floats2half2_rn(st[j], t2[j]);
                s_raw[r * PITCH + SWC(c)] = c2u(cl);
            }
        }
    }
    __syncthreads();                                           // B1

    // ---- Phase 2: horizontal 7-sum IN PLACE, half2 SIMD ----
    {
        const int g2 = tid & 15;     // output cols 4*g2 .. 4*g2+3
        const int r2 = tid >> 4;     // 0..15
        int o[10];
#pragma unroll
        for (int i = 0; i < 10; i++) o[i] = SWC(4 * g2 + i);

#pragma unroll
        for (int pss = 0; pss < 2; pss++) {
            int r = pss * 16 + r2;
            bool active = (r < HR);
            Cell h0, h1, h2, h3;
            if (active) {
                const uint2* row = s_raw + r * PITCH;
                Cell e0 = u2c(row[o[0]]), e1 = u2c(row[o[1]]), e2 = u2c(row[o[2]]);
                Cell e3 = u2c(row[o[3]]), e4 = u2c(row[o[4]]);
                Cell e5 = u2c(row[o[5]]), e6 = u2c(row[o[6]]);
                Cell e7 = u2c(row[o[7]]), e8 = u2c(row[o[8]]), e9 = u2c(row[o[9]]);
                h0 = cadd(cadd(cadd(e0, e1), cadd(e2, e3)),
                          cadd(cadd(e4, e5), e6));
                h1 = cslide(h0, e7, e0);
                h2 = cslide(h1, e8, e1);
                h3 = cslide(h2, e9, e2);
            }
            __syncthreads();                                   // B2 / B3
            if (active) {
                uint2* row = s_raw + r * PITCH;
                row[o[0]] = c2u(h0);
                row[o[1]] = c2u(h1);
                row[o[2]] = c2u(h2);
                row[o[3]] = c2u(h3);
            }
        }
    }
    __syncthreads();                                           // B4

    // ---- Phase 3: vertical 7-sum (half2) + std + smooth-L1 (fp32) ----
    float acc = 0.f;
    {
        const int c3 = tid & 63;     // output col 0..63
        const int rg = tid >> 6;     // 0..3 -> output rows 4rg..4rg+3
        const uint2* col = s_raw + SWC(c3);
        const int rb = rg * 4;

        Cell v[10];
#pragma unroll
        for (int i = 0; i < 7; i++) v[i] = u2c(col[(rb + i) * PITCH]);
        Cell w = cadd(cadd(cadd(v[0], v[1]), cadd(v[2], v[3])),
                      cadd(cadd(v[4], v[5]), v[6]));
#pragma unroll
        for (int q = 0; q < 4; q++) {
            float2 fp = __half22float2(w.p);   // (S, S2) pred
            float2 ft = __half22float2(w.t);   // (S, S2) tgt
            float mup  = fp.x * NINV;
            float varp = fp.y * NINV - mup * mup;
            float sdp  = sqrtf(varp + EPS);
            float mut  = ft.x * NINV;
            float vart = ft.y * NINV - mut * mut;
            float sdt  = sqrtf(vart + EPS);
            float d  = sdp - sdt;
            float ad = fabsf(d);
            acc += (ad < 1.0f) ? 0.5f * d * d : (ad - 0.5f);
            if (q < 3) {
                v[7 + q] = u2c(col[(rb + 7 + q) * PITCH]);
                w = cslide(w, v[7 + q], v[q]);
            }
        }
    }

    // ---- block reduction: warp shuffle + one barrier ----
#pragma unroll
    for (int off = 16; off > 0; off >>= 1)
        acc += __shfl_down_sync(0xffffffffu, acc, off);
    if (lane == 0) s_warp[wid] = acc;
    __syncthreads();                                           // B5

    const int pidx = blockIdx.z * 256 + blockIdx.y * 8 + blockIdx.x;
    if (wid == 0) {
        float a = (lane < 8) ? s_warp[lane] : 0.f;
#pragma unroll
        for (int off = 4; off > 0; off >>= 1)
            a += __shfl_down_sync(0xffffffffu, a, off);
        if (lane == 0) {
            g_partials[pidx] = a;
            __threadfence();
            unsigned int prev = atomicInc(&g_count, NBLK - 1);  // wraps to 0
            s_is_last = (prev == NBLK - 1);
        }
    }
    __syncthreads();                                           // B6

    // ---- last block: final deterministic reduction ----
    if (s_is_last) {
        float a = 0.f;
#pragma unroll
        for (int i = 0; i < NBLK / 256; i++)
            a += g_partials[tid + i * 256];
#pragma unroll
        for (int off = 16; off > 0; off >>= 1)
            a += __shfl_down_sync(0xffffffffu, a, off);
        if (lane == 0) s_warp[wid] = a;
        __syncthreads();
        if (tid == 0) {
            float s = 0.f;
#pragma unroll
            for (int i = 0; i < 8; i++) s += s_warp[i];
            out[0] = s * (1.0f / NPIX);
        }
    }
}

extern "C" void kernel_launch(void* const* d_in, const int* in_sizes, int n_in,
                              void* d_out, int out_size)
{
    const float* pred = (const float*)d_in[0];
    const float* tgt  = (const float*)d_in[1];
    float* out = (float*)d_out;

    dim3 grid(8, 32, 16);   // x tiles (64 wide), y tiles (16 tall), batch
    dim3 block(32, 8);
    dist_loss_main<<<grid, block>>>(pred, tgt, out);
}